// round 8
// baseline (speedup 1.0000x reference)
#include <cuda_runtime.h>
#include <cuda_bf16.h>

// LoRA: out[b,s,o] = scaling * sum_r ( sum_i x[b,s,i] * A[r,i] ) * B[o,r]
// x: [4, 8192, 1024] f32   A: [4, 1024] f32   B: [1024, 4] f32   scaling = 0.25
//
// R4 reg-cap-32 -> MLP 1 (232us). R5 no cap -> occ 11% (69us). R6 cap 84 ->
// L1tex 82.6% (49.9us). R7 2-row LDS amortization -> DRAM 66%, issue 28%,
// fma 18% (47.5us/41.3 ncu). R8: packed fp32 (fma.rn.f32x2 -> SASS FFMA2,
// PTX-only) halves all FMA warp-instructions in both passes, shrinking the
// per-iteration compute phase so load bursts recur faster.

#define LORA_NROWS   (4 * 8192)   // 32768 token rows
#define LORA_NF4     256          // 1024 floats / 4 -> 16B chunks per row
#define LORA_BLOCK   256
#define LORA_WARPS   8
#define LORA_GRID    1024
#define LORA_NWARPS  (LORA_GRID * LORA_WARPS)      // 8192 warps
#define LORA_PAIRS   (LORA_NROWS / 2)              // 16384 row-pairs
#define LORA_SCALE   0.25f

// ---- packed fp32x2 helpers (SASS: FFMA2 / FMUL2; ptxas won't emit from C++) ----
__device__ __forceinline__ unsigned long long f2fma(unsigned long long a,
                                                    unsigned long long b,
                                                    unsigned long long c) {
    unsigned long long d;
    asm("fma.rn.f32x2 %0, %1, %2, %3;" : "=l"(d) : "l"(a), "l"(b), "l"(c));
    return d;
}
__device__ __forceinline__ unsigned long long f2mul(unsigned long long a,
                                                    unsigned long long b) {
    unsigned long long d;
    asm("mul.rn.f32x2 %0, %1, %2;" : "=l"(d) : "l"(a), "l"(b));
    return d;
}
__device__ __forceinline__ unsigned long long pk2(float lo, float hi) {
    unsigned long long r;
    asm("mov.b64 %0, {%1, %2};" : "=l"(r) : "f"(lo), "f"(hi));
    return r;
}
__device__ __forceinline__ float2 unpk2(unsigned long long v) {
    float2 f;
    asm("mov.b64 {%0, %1}, %2;" : "=f"(f.x), "=f"(f.y) : "l"(v));
    return f;
}
// 16B streaming global load/store as two packed-f32x2 lanes
__device__ __forceinline__ ulonglong2 ldcs16(const ulonglong2* p) {
    ulonglong2 v;
    asm("ld.global.cs.v2.u64 {%0, %1}, [%2];" : "=l"(v.x), "=l"(v.y) : "l"(p));
    return v;
}
__device__ __forceinline__ void stcs16(ulonglong2* p, ulonglong2 v) {
    asm("st.global.cs.v2.u64 [%0], {%1, %2};" :: "l"(p), "l"(v.x), "l"(v.y) : "memory");
}

__global__ __launch_bounds__(LORA_BLOCK, 2)
void lora_fused_kernel(const float* __restrict__ x,
                       const float* __restrict__ A,
                       const float* __restrict__ B,
                       float* __restrict__ out)
{
    __shared__ float sA[4 * 1024];   // rank-major, same as global A layout
    __shared__ float sBt[4 * 1024];  // TRANSPOSED: sBt[r*1024 + o] = B[o*4 + r]

    const int tid = threadIdx.x;

    // ---- Stage A (direct float4 copy) and B (transpose) into smem ----
    {
        const float4* A4  = reinterpret_cast<const float4*>(A);
        float4*       sA4 = reinterpret_cast<float4*>(sA);
        #pragma unroll
        for (int i = 0; i < 4; i++)
            sA4[tid + i * 256] = A4[tid + i * 256];

        const float4* B4 = reinterpret_cast<const float4*>(B);  // one float4 = one B row
        #pragma unroll
        for (int i = 0; i < 4; i++) {
            int o = tid + i * 256;
            float4 b = B4[o];
            sBt[0 * 1024 + o] = b.x;
            sBt[1 * 1024 + o] = b.y;
            sBt[2 * 1024 + o] = b.z;
            sBt[3 * 1024 + o] = b.w;
        }
    }
    __syncthreads();

    const int lane = tid & 31;
    const int wid  = tid >> 5;
    const int warp_global = blockIdx.x * LORA_WARPS + wid;

    // 16B views of the smem tiles (LDS.128, conflict-free: stride 16B per lane)
    const ulonglong2* sA2 = reinterpret_cast<const ulonglong2*>(sA);
    const ulonglong2* sB0 = reinterpret_cast<const ulonglong2*>(sBt);
    const ulonglong2* sB1 = reinterpret_cast<const ulonglong2*>(sBt + 1024);
    const ulonglong2* sB2 = reinterpret_cast<const ulonglong2*>(sBt + 2048);
    const ulonglong2* sB3 = reinterpret_cast<const ulonglong2*>(sBt + 3072);

    for (int pair = warp_global; pair < LORA_PAIRS; pair += LORA_NWARPS) {
        const size_t row0 = (size_t)pair * 2;

        const ulonglong2* xr0 = reinterpret_cast<const ulonglong2*>(x) + row0 * LORA_NF4;
        const ulonglong2* xr1 = xr0 + LORA_NF4;

        // ---- Prefetch both rows: 16 independent LDG.128 (MLP=16) ----
        ulonglong2 xv0[8], xv1[8];
        #pragma unroll
        for (int j = 0; j < 8; j++) xv0[j] = ldcs16(&xr0[j * 32 + lane]);
        #pragma unroll
        for (int j = 0; j < 8; j++) xv1[j] = ldcs16(&xr1[j * 32 + lane]);

        // ---- Pass 1: packed rank dot-products, A tile shared by both rows ----
        unsigned long long a00 = 0, a01 = 0, a02 = 0, a03 = 0;  // row0, ranks 0..3
        unsigned long long a10 = 0, a11 = 0, a12 = 0, a13 = 0;  // row1
        #pragma unroll
        for (int j = 0; j < 8; j++) {
            int idx = j * 32 + lane;
            ulonglong2 t0 = sA2[0 * 256 + idx];
            ulonglong2 t1 = sA2[1 * 256 + idx];
            ulonglong2 t2 = sA2[2 * 256 + idx];
            ulonglong2 t3 = sA2[3 * 256 + idx];
            a00 = f2fma(xv0[j].x, t0.x, a00); a00 = f2fma(xv0[j].y, t0.y, a00);
            a01 = f2fma(xv0[j].x, t1.x, a01); a01 = f2fma(xv0[j].y, t1.y, a01);
            a02 = f2fma(xv0[j].x, t2.x, a02); a02 = f2fma(xv0[j].y, t2.y, a02);
            a03 = f2fma(xv0[j].x, t3.x, a03); a03 = f2fma(xv0[j].y, t3.y, a03);
            a10 = f2fma(xv1[j].x, t0.x, a10); a10 = f2fma(xv1[j].y, t0.y, a10);
            a11 = f2fma(xv1[j].x, t1.x, a11); a11 = f2fma(xv1[j].y, t1.y, a11);
            a12 = f2fma(xv1[j].x, t2.x, a12); a12 = f2fma(xv1[j].y, t2.y, a12);
            a13 = f2fma(xv1[j].x, t3.x, a13); a13 = f2fma(xv1[j].y, t3.y, a13);
        }

        // ---- Horizontal fold lo+hi, then warp butterfly on 8 scalars ----
        float2 f;
        f = unpk2(a00); float p0 = f.x + f.y;
        f = unpk2(a01); float p1 = f.x + f.y;
        f = unpk2(a02); float p2 = f.x + f.y;
        f = unpk2(a03); float p3 = f.x + f.y;
        f = unpk2(a10); float q0 = f.x + f.y;
        f = unpk2(a11); float q1 = f.x + f.y;
        f = unpk2(a12); float q2 = f.x + f.y;
        f = unpk2(a13); float q3 = f.x + f.y;

        #pragma unroll
        for (int off = 16; off > 0; off >>= 1) {
            p0 += __shfl_xor_sync(0xffffffffu, p0, off);
            p1 += __shfl_xor_sync(0xffffffffu, p1, off);
            p2 += __shfl_xor_sync(0xffffffffu, p2, off);
            p3 += __shfl_xor_sync(0xffffffffu, p3, off);
            q0 += __shfl_xor_sync(0xffffffffu, q0, off);
            q1 += __shfl_xor_sync(0xffffffffu, q1, off);
            q2 += __shfl_xor_sync(0xffffffffu, q2, off);
            q3 += __shfl_xor_sync(0xffffffffu, q3, off);
        }
        p0 *= LORA_SCALE; p1 *= LORA_SCALE; p2 *= LORA_SCALE; p3 *= LORA_SCALE;
        q0 *= LORA_SCALE; q1 *= LORA_SCALE; q2 *= LORA_SCALE; q3 *= LORA_SCALE;

        // Broadcast packs (once per pair)
        const unsigned long long P0 = pk2(p0, p0), P1 = pk2(p1, p1),
                                 P2 = pk2(p2, p2), P3 = pk2(p3, p3);
        const unsigned long long Q0 = pk2(q0, q0), Q1 = pk2(q1, q1),
                                 Q2 = pk2(q2, q2), Q3 = pk2(q3, q3);

        // ---- Pass 2: packed expansion, B tile shared by both rows ----
        ulonglong2* orow0 = reinterpret_cast<ulonglong2*>(out) + row0 * LORA_NF4;
        ulonglong2* orow1 = orow0 + LORA_NF4;
        #pragma unroll
        for (int j = 0; j < 8; j++) {
            int idx = j * 32 + lane;
            ulonglong2 b0 = sB0[idx];
            ulonglong2 b1 = sB1[idx];
            ulonglong2 b2 = sB2[idx];
            ulonglong2 b3 = sB3[idx];
            ulonglong2 o0, o1;
            o0.x = f2fma(P0, b0.x, f2fma(P1, b1.x, f2fma(P2, b2.x, f2mul(P3, b3.x))));
            o0.y = f2fma(P0, b0.y, f2fma(P1, b1.y, f2fma(P2, b2.y, f2mul(P3, b3.y))));
            o1.x = f2fma(Q0, b0.x, f2fma(Q1, b1.x, f2fma(Q2, b2.x, f2mul(Q3, b3.x))));
            o1.y = f2fma(Q0, b0.y, f2fma(Q1, b1.y, f2fma(Q2, b2.y, f2mul(Q3, b3.y))));
            stcs16(&orow0[idx], o0);
            stcs16(&orow1[idx], o1);
        }
    }
}

extern "C" void kernel_launch(void* const* d_in, const int* in_sizes, int n_in,
                              void* d_out, int out_size)
{
    const float* x = (const float*)d_in[0];   // [4, 8192, 1024]
    const float* A = (const float*)d_in[1];   // [4, 1024]
    const float* B = (const float*)d_in[2];   // [1024, 4]
    float* out     = (float*)d_out;           // [4, 8192, 1024]

    lora_fused_kernel<<<LORA_GRID, LORA_BLOCK>>>(x, A, B, out);
}